// round 2
// baseline (speedup 1.0000x reference)
#include <cuda_runtime.h>
#include <stdint.h>

// Problem constants
#define BB 16
#define NN 25200
#define CC 80
#define MAXDET 100
#define CAP 25216           // >= NN, padded

// Output layout (flattened concat, float32):
//   boxes  [16][100][4] @ 0       (6400)
//   scores [16][100]    @ 6400    (1600)
//   classes[16][100][80]@ 8000    (128000)
//   counts [16]         @ 136000  (16)
#define OFF_BOX   0
#define OFF_SCORE 6400
#define OFF_CLS   8000
#define OFF_CNT   136000

typedef unsigned long long ull;

// 32-byte element: a = (x0,y0,x1,y1), b = (score, idx_bits, area, 0)
struct __align__(16) El8 { float4 a; float4 b; };

// ---------------- scratch (__device__ globals: no allocs) -------------------
__device__ El8  g_elA[BB][CAP];      // ping
__device__ El8  g_elB[BB][CAP];      // pong
__device__ int  g_count[BB];
__device__ float4 g_selbox[BB][MAXDET];
__device__ float  g_selscore[BB][MAXDET];
__device__ int    g_selidx[BB][MAXDET];
__device__ int    g_selcount[BB];

// ---------------------------------------------------------------------------
// Kernel 0: reset persistent counters (device globals survive graph replays).
// ---------------------------------------------------------------------------
__global__ void reset_kernel()
{
    if (threadIdx.x < BB) {
        g_count[threadIdx.x] = 0;
        g_selcount[threadIdx.x] = 0;
    }
}

// ---------------------------------------------------------------------------
// Kernel 1: UNORDERED compaction (order-free: tie-breaks live in the u64 key).
// Fully parallel grid, warp-aggregated atomics. grid = (ceil(NN/256), BB).
// ---------------------------------------------------------------------------
__global__ void __launch_bounds__(256)
compact_kernel(const float* __restrict__ boxes, const float* __restrict__ obj)
{
    const int b = blockIdx.y;
    const int n = blockIdx.x * 256 + threadIdx.x;
    const int lane = threadIdx.x & 31;

    bool p = false;
    float sc = 0.0f;
    if (n < NN) {
        sc = obj[(size_t)b * NN + n];
        p = (sc >= 0.5f);
    }
    unsigned ball = __ballot_sync(0xffffffffu, p);
    int cnt = __popc(ball);
    int base = 0;
    if (lane == 0 && cnt) base = atomicAdd(&g_count[b], cnt);
    base = __shfl_sync(0xffffffffu, base, 0);

    if (p) {
        const float4* bx4 = reinterpret_cast<const float4*>(boxes);
        float4 v = bx4[(size_t)b * NN + n];        // (x, y, w, h)
        float hx = 0.5f * v.z;
        float hy = 0.5f * v.w;
        float x0 = v.x - hx, y0 = v.y - hy;
        float x1 = v.x + hx, y1 = v.y + hy;
        float a2 = (x1 - x0) * (y1 - y0);          // same formula as R1
        int pos = base + __popc(ball & ((1u << lane) - 1u));
        g_elA[b][pos].a = make_float4(x0, y0, x1, y1);
        g_elA[b][pos].b = make_float4(sc, __int_as_float(n), a2, 0.0f);
    }
}

// ---------------------------------------------------------------------------
// Kernel 2: greedy NMS with per-round live-set re-compaction (ping-pong).
// One CTA per batch, 1024 threads, 3 syncthreads per round.
// Round: scan src (suppress vs prev winner, build local argmax key, survive
// mask) -> block reduce (argmax key + survivor-count scan) -> owner publishes
// winner -> scatter survivors (minus winner) densely into dst.
// ---------------------------------------------------------------------------
__global__ void __launch_bounds__(1024, 1)
nms_kernel()
{
    const int b    = blockIdx.x;
    const int tid  = threadIdx.x;
    const int wid  = tid >> 5;
    const int lane = tid & 31;

    __shared__ ull    s_wkey[32];
    __shared__ int    s_wcnt[32];
    __shared__ int    s_wbase[32];
    __shared__ ull    s_winkey;
    __shared__ int    s_nact;
    __shared__ float4 s_win;
    __shared__ float  s_warea;

    int nAct = g_count[b];
    bool haveBest = false;

    for (int it = 0; it < MAXDET; it++) {
        if (nAct == 0) break;

        const El8* __restrict__ src = (it & 1) ? g_elB[b] : g_elA[b];
        El8*       __restrict__ dst = (it & 1) ? g_elA[b] : g_elB[b];

        float4 W = make_float4(0.f, 0.f, 0.f, 0.f);
        float  Wa = 0.f;
        if (haveBest) { W = s_win; Wa = s_warea; }

        const int kmax = (nAct + 1023) >> 10;

        // ---- phase 1: suppress + local argmax -------------------------------
        unsigned mask = 0u;
        ull key = 0ull;
        int bestK = 0;
        for (int k = 0; k < kmax; k++) {
            int slot = (k << 10) + tid;
            if (slot < nAct) {
                float4 c = src[slot].a;
                float4 m = src[slot].b;
                bool keep = true;
                if (haveBest) {
                    float ltx = fmaxf(W.x, c.x);
                    float lty = fmaxf(W.y, c.y);
                    float rbx = fminf(W.z, c.z);
                    float rby = fminf(W.w, c.w);
                    float w = fmaxf(rbx - ltx, 0.0f);
                    float h = fmaxf(rby - lty, 0.0f);
                    float inter = w * h;
                    float denom = Wa + m.z - inter + 1e-9f;  // same bits as R1
                    keep = !(inter > 0.5f * denom);
                }
                if (keep) {
                    mask |= (1u << k);
                    ull kk = ((ull)__float_as_uint(m.x) << 32)
                           | (ull)(0xFFFFFFFFu - __float_as_uint(m.y));
                    if (kk > key) { key = kk; bestK = k; }
                }
            }
        }

        // ---- phase 2: block reduce (argmax + survivor-count scan) -----------
        int wtot = __reduce_add_sync(0xffffffffu, __popc(mask));
        ull wk = key;
        #pragma unroll
        for (int off = 16; off; off >>= 1) {
            ull o = __shfl_xor_sync(0xffffffffu, wk, off);
            if (o > wk) wk = o;
        }
        if (lane == 0) { s_wcnt[wid] = wtot; s_wkey[wid] = wk; }
        __syncthreads();                                   // sync 1

        if (wid == 0) {
            int c2 = s_wcnt[lane];
            ull k2 = s_wkey[lane];
            ull km = k2;
            #pragma unroll
            for (int off = 16; off; off >>= 1) {
                ull o = __shfl_xor_sync(0xffffffffu, km, off);
                if (o > km) km = o;
            }
            unsigned wball = __ballot_sync(0xffffffffu, k2 == km);
            int wstar = __ffs(wball) - 1;
            // winner (if any) is removed from the next live set
            int adj = c2 - ((lane == wstar && km != 0ull) ? 1 : 0);
            int inc = adj;
            #pragma unroll
            for (int off = 1; off < 32; off <<= 1) {
                int o = __shfl_up_sync(0xffffffffu, inc, off);
                if (lane >= off) inc += o;
            }
            s_wbase[lane] = inc - adj;                      // exclusive base
            if (lane == 31) s_nact = inc;                   // new live count
            if (lane == 0)  s_winkey = km;
        }
        __syncthreads();                                   // sync 2

        const ull winkey = s_winkey;
        const int base   = s_wbase[wid];

        // ---- owner publishes winner + writes this round's output ------------
        if (winkey != 0ull && key == winkey) {              // unique thread
            int slot = (bestK << 10) + tid;
            float4 c = src[slot].a;
            float4 m = src[slot].b;
            s_win   = c;
            s_warea = m.z;
            mask &= ~(1u << bestK);                         // exclude winner
            g_selbox[b][it]   = c;
            g_selscore[b][it] = m.x;
            g_selidx[b][it]   = (int)__float_as_uint(m.y);
            g_selcount[b]     = it + 1;
        }

        // ---- phase 3: dense scatter of survivors into dst -------------------
        int running = base;
        for (int k = 0; k < kmax; k++) {
            int slot = (k << 10) + tid;
            bool mine = (mask >> k) & 1u;
            unsigned ball = __ballot_sync(0xffffffffu, mine);
            if (mine) {
                int pos = running + __popc(ball & ((1u << lane) - 1u));
                dst[pos] = src[slot];
            }
            running += __popc(ball);
        }

        haveBest = true;
        __syncthreads();                                   // sync 3
        nAct = s_nact;
    }
}

// ---------------------------------------------------------------------------
// Kernel 3: write outputs. One warp per (batch, det). Zeros past count.
// ---------------------------------------------------------------------------
__global__ void __launch_bounds__(256)
write_kernel(const float* __restrict__ class_prob, float* __restrict__ out)
{
    int gw   = (blockIdx.x * blockDim.x + threadIdx.x) >> 5;
    int lane = threadIdx.x & 31;

    if (gw < BB * MAXDET) {
        int b = gw / MAXDET;
        int i = gw - b * MAXDET;
        bool valid = (i < g_selcount[b]);

        float4 box = make_float4(0.f, 0.f, 0.f, 0.f);
        float scv = 0.0f;
        int orig = 0;
        if (valid) {
            box  = g_selbox[b][i];
            scv  = g_selscore[b][i];
            orig = g_selidx[b][i];
        }

        if (lane == 0) {
            float* p = out + OFF_BOX + (size_t)(b * MAXDET + i) * 4;
            p[0] = box.x; p[1] = box.y; p[2] = box.z; p[3] = box.w;
            out[OFF_SCORE + b * MAXDET + i] = scv;
        }
        const float* cp = class_prob + ((size_t)b * NN + orig) * CC;
        float* co = out + OFF_CLS + (size_t)(b * MAXDET + i) * CC;
        #pragma unroll
        for (int c = lane; c < CC; c += 32) {
            co[c] = valid ? cp[c] : 0.0f;
        }
    }

    if (blockIdx.x == 0 && threadIdx.x < BB) {
        out[OFF_CNT + threadIdx.x] = (float)g_selcount[threadIdx.x];
    }
}

// ---------------------------------------------------------------------------
extern "C" void kernel_launch(void* const* d_in, const int* in_sizes, int n_in,
                              void* d_out, int out_size)
{
    const float* boxes = (const float*)d_in[0];   // (16, 25200, 4)
    const float* obj   = (const float*)d_in[1];   // (16, 25200, 1)
    const float* cls   = (const float*)d_in[2];   // (16, 25200, 80)
    float* out = (float*)d_out;

    reset_kernel<<<1, 32>>>();
    compact_kernel<<<dim3((NN + 255) / 256, BB), 256>>>(boxes, obj);
    nms_kernel<<<BB, 1024>>>();
    write_kernel<<<(BB * MAXDET * 32 + 255) / 256, 256>>>(cls, out);
}

// round 3
// speedup vs baseline: 4.8083x; 4.8083x over previous
#include <cuda_runtime.h>
#include <stdint.h>

// Problem constants
#define BB 16
#define NN 25200
#define CC 80
#define MAXDET 100
#define CAP_S 13312          // smem-resident capacity (13 * 1024)
#define KS 13                // slots per thread in smem region

// Output layout (flattened concat, float32):
#define OFF_BOX   0
#define OFF_SCORE 6400
#define OFF_CLS   8000
#define OFF_CNT   136000

typedef unsigned long long ull;

// ---------------- scratch (__device__ globals: no allocs) -------------------
__device__ float4 g_cor[BB][NN];     // compacted corners (x0,y0,x1,y1)
__device__ float2 g_meta[BB][NN];    // (score, orig_idx bits)
__device__ int    g_count[BB];
__device__ float4 g_selbox[BB][MAXDET];
__device__ float  g_selscore[BB][MAXDET];
__device__ int    g_selidx[BB][MAXDET];
__device__ int    g_selcount[BB];

// ---------------------------------------------------------------------------
__global__ void reset_kernel()
{
    if (threadIdx.x < BB) {
        g_count[threadIdx.x] = 0;
        g_selcount[threadIdx.x] = 0;
    }
}

// ---------------------------------------------------------------------------
// Kernel 1: UNORDERED parallel compaction (tie-breaks live in the u64 key).
// ---------------------------------------------------------------------------
__global__ void __launch_bounds__(256)
compact_kernel(const float* __restrict__ boxes, const float* __restrict__ obj)
{
    const int b = blockIdx.y;
    const int n = blockIdx.x * 256 + threadIdx.x;
    const int lane = threadIdx.x & 31;

    bool p = false;
    float sc = 0.0f;
    if (n < NN) {
        sc = obj[(size_t)b * NN + n];
        p = (sc >= 0.5f);
    }
    unsigned ball = __ballot_sync(0xffffffffu, p);
    int cnt = __popc(ball);
    int base = 0;
    if (lane == 0 && cnt) base = atomicAdd(&g_count[b], cnt);
    base = __shfl_sync(0xffffffffu, base, 0);

    if (p) {
        const float4* bx4 = reinterpret_cast<const float4*>(boxes);
        float4 v = bx4[(size_t)b * NN + n];        // (x, y, w, h)
        float hx = 0.5f * v.z;
        float hy = 0.5f * v.w;
        int pos = base + __popc(ball & ((1u << lane) - 1u));
        g_cor[b][pos]  = make_float4(v.x - hx, v.y - hy, v.x + hx, v.y + hy);
        g_meta[b][pos] = make_float2(sc, __int_as_float(n));
    }
}

// ---------------------------------------------------------------------------
// Kernel 2: greedy NMS, corners resident in dynamic SMEM, keys in registers.
// One CTA per batch, 1024 threads, 2 syncthreads per round.
// ---------------------------------------------------------------------------
extern __shared__ float4 sm[];       // CAP_S corners

__global__ void __launch_bounds__(1024, 1)
nms_kernel()
{
    const int b    = blockIdx.x;
    const int tid  = threadIdx.x;
    const int wid  = tid >> 5;
    const int lane = tid & 31;

    __shared__ ull  s_wkey[32];
    __shared__ int  s_wslot[32];
    __shared__ ull  s_winkey;
    __shared__ int  s_winslot;
    __shared__ float4 s_ovf;

    const int cnt = g_count[b];

    // ---- load: corners -> smem, keys -> registers ---------------------------
    ull key[KS];
    unsigned mask = 0u;
    #pragma unroll
    for (int k = 0; k < KS; k++) {
        int slot = (k << 10) + tid;
        key[k] = 0ull;
        if (slot < cnt) {
            sm[slot] = g_cor[b][slot];
            float2 m = g_meta[b][slot];
            key[k] = ((ull)__float_as_uint(m.x) << 32)
                   | (ull)(0xFFFFFFFFu - __float_as_uint(m.y));
            mask |= (1u << k);
        } else {
            sm[slot] = make_float4(0.f, 0.f, 0.f, 0.f);
        }
    }
    // overflow region (cnt > CAP_S): statistically never; correctness insurance
    unsigned mask2 = 0u;
    const int kg_max = (cnt > CAP_S) ? ((cnt - CAP_S + 1023) >> 10) : 0;
    for (int kg = 0; kg < kg_max; kg++) {
        if (CAP_S + (kg << 10) + tid < cnt) mask2 |= (1u << kg);
    }
    __syncthreads();

    // W = sentinel box that overlaps nothing; Wa = 0 -> round 0 suppresses none
    float4 W = make_float4(2.f, 2.f, 2.f, 2.f);
    float Wa = 0.f;

    for (int it = 0; it < MAXDET; it++) {
        ull bk = 0ull;
        int bslot = 0;

        // ---- fused suppress + local argmax over smem slots ------------------
        #pragma unroll
        for (int k = 0; k < KS; k++) {
            int slot = (k << 10) + tid;
            float4 c = sm[slot];
            float ltx = fmaxf(W.x, c.x);
            float lty = fmaxf(W.y, c.y);
            float rbx = fminf(W.z, c.z);
            float rby = fminf(W.w, c.w);
            float w = fmaxf(rbx - ltx, 0.0f);
            float h = fmaxf(rby - lty, 0.0f);
            float inter = w * h;
            float a2 = (c.z - c.x) * (c.w - c.y);
            float denom = Wa + a2 - inter + 1e-9f;   // exact R1 expression
            bool sup = inter > 0.5f * denom;
            if (sup) mask &= ~(1u << k);
            if (((mask >> k) & 1u) && key[k] > bk) { bk = key[k]; bslot = slot; }
        }
        // ---- overflow slots from global (normally kg_max == 0) --------------
        for (int kg = 0; kg < kg_max; kg++) {
            if ((mask2 >> kg) & 1u) {
                int slot = CAP_S + (kg << 10) + tid;
                float4 c = g_cor[b][slot];
                float ltx = fmaxf(W.x, c.x);
                float lty = fmaxf(W.y, c.y);
                float rbx = fminf(W.z, c.z);
                float rby = fminf(W.w, c.w);
                float w = fmaxf(rbx - ltx, 0.0f);
                float h = fmaxf(rby - lty, 0.0f);
                float inter = w * h;
                float a2 = (c.z - c.x) * (c.w - c.y);
                float denom = Wa + a2 - inter + 1e-9f;
                if (inter > 0.5f * denom) {
                    mask2 &= ~(1u << kg);
                } else {
                    float2 m = g_meta[b][slot];
                    ull kk = ((ull)__float_as_uint(m.x) << 32)
                           | (ull)(0xFFFFFFFFu - __float_as_uint(m.y));
                    if (kk > bk) { bk = kk; bslot = slot; }
                }
            }
        }

        // ---- block argmax: (key, slot) --------------------------------------
        #pragma unroll
        for (int off = 16; off; off >>= 1) {
            ull ok = __shfl_down_sync(0xffffffffu, bk, off);
            int os = __shfl_down_sync(0xffffffffu, bslot, off);
            if (ok > bk) { bk = ok; bslot = os; }
        }
        if (lane == 0) { s_wkey[wid] = bk; s_wslot[wid] = bslot; }
        __syncthreads();                               // sync 1

        if (wid == 0) {
            ull k2 = s_wkey[lane];
            int sl2 = s_wslot[lane];
            #pragma unroll
            for (int off = 16; off; off >>= 1) {
                ull ok = __shfl_down_sync(0xffffffffu, k2, off);
                int os = __shfl_down_sync(0xffffffffu, sl2, off);
                if (ok > k2) { k2 = ok; sl2 = os; }
            }
            if (lane == 0) { s_winkey = k2; s_winslot = sl2; }
        }
        __syncthreads();                               // sync 2

        const ull wk = s_winkey;
        if (wk == 0ull) break;                         // no active candidates
        const int ws = s_winslot;

        // winner corners: broadcast LDS (or rare global path)
        if (ws < CAP_S) {
            W = sm[ws];
        } else {
            if ((ws & 1023) == tid) s_ovf = g_cor[b][ws];
            __syncthreads();                           // rare path only
            W = s_ovf;
        }
        Wa = (W.z - W.x) * (W.w - W.y);                // same bits as stored area

        if (tid == 0) {
            g_selbox[b][it]   = W;
            g_selscore[b][it] = __uint_as_float((unsigned)(wk >> 32));
            g_selidx[b][it]   = (int)(0xFFFFFFFFu - (unsigned)wk);
            g_selcount[b]     = it + 1;
        }
        // winner self-clear by owning thread
        if ((ws & 1023) == tid) {
            if (ws < CAP_S) mask  &= ~(1u << (ws >> 10));
            else            mask2 &= ~(1u << ((ws - CAP_S) >> 10));
        }
    }
}

// ---------------------------------------------------------------------------
// Kernel 3: write outputs. One warp per (batch, det). Zeros past count.
// ---------------------------------------------------------------------------
__global__ void __launch_bounds__(256)
write_kernel(const float* __restrict__ class_prob, float* __restrict__ out)
{
    int gw   = (blockIdx.x * blockDim.x + threadIdx.x) >> 5;
    int lane = threadIdx.x & 31;

    if (gw < BB * MAXDET) {
        int b = gw / MAXDET;
        int i = gw - b * MAXDET;
        bool valid = (i < g_selcount[b]);

        float4 box = make_float4(0.f, 0.f, 0.f, 0.f);
        float scv = 0.0f;
        int orig = 0;
        if (valid) {
            box  = g_selbox[b][i];
            scv  = g_selscore[b][i];
            orig = g_selidx[b][i];
        }

        if (lane == 0) {
            float* p = out + OFF_BOX + (size_t)(b * MAXDET + i) * 4;
            p[0] = box.x; p[1] = box.y; p[2] = box.z; p[3] = box.w;
            out[OFF_SCORE + b * MAXDET + i] = scv;
        }
        const float* cp = class_prob + ((size_t)b * NN + orig) * CC;
        float* co = out + OFF_CLS + (size_t)(b * MAXDET + i) * CC;
        #pragma unroll
        for (int c = lane; c < CC; c += 32) {
            co[c] = valid ? cp[c] : 0.0f;
        }
    }

    if (blockIdx.x == 0 && threadIdx.x < BB) {
        out[OFF_CNT + threadIdx.x] = (float)g_selcount[threadIdx.x];
    }
}

// ---------------------------------------------------------------------------
extern "C" void kernel_launch(void* const* d_in, const int* in_sizes, int n_in,
                              void* d_out, int out_size)
{
    const float* boxes = (const float*)d_in[0];   // (16, 25200, 4)
    const float* obj   = (const float*)d_in[1];   // (16, 25200, 1)
    const float* cls   = (const float*)d_in[2];   // (16, 25200, 80)
    float* out = (float*)d_out;

    static bool attr_done = false;
    if (!attr_done) {
        cudaFuncSetAttribute(nms_kernel,
                             cudaFuncAttributeMaxDynamicSharedMemorySize,
                             CAP_S * (int)sizeof(float4));
        attr_done = true;
    }

    reset_kernel<<<1, 32>>>();
    compact_kernel<<<dim3((NN + 255) / 256, BB), 256>>>(boxes, obj);
    nms_kernel<<<BB, 1024, CAP_S * sizeof(float4)>>>();
    write_kernel<<<(BB * MAXDET * 32 + 255) / 256, 256>>>(cls, out);
}

// round 4
// speedup vs baseline: 8.9998x; 1.8717x over previous
#include <cuda_runtime.h>
#include <stdint.h>

// Problem constants
#define BB 16
#define NN 25200
#define CC 80
#define MAXDET 100
#define CAP_S 13312          // fallback smem capacity (13 * 1024)
#define KS 13                // fallback slots per thread
#define T_HI 0.92f           // hi-subset threshold (expected ~2016 of 25200)
#define CAP_HI 4096          // hi-subset capacity (4 * 1024)
#define KH 4                 // hi slots per thread (max)

// Output layout (flattened concat, float32):
#define OFF_BOX   0
#define OFF_SCORE 6400
#define OFF_CLS   8000
#define OFF_CNT   136000

typedef unsigned long long ull;

// ---------------- scratch (__device__ globals: no allocs) -------------------
__device__ float4 g_cor[BB][NN];        // full compacted corners
__device__ float2 g_meta[BB][NN];       // full (score, idx bits)
__device__ int    g_count[BB];
__device__ float4 g_hicor[BB][CAP_HI];  // hi-subset corners
__device__ ull    g_hikey[BB][CAP_HI];  // hi-subset keys
__device__ int    g_hicount[BB];
__device__ int    g_done[BB];           // 1 => hi path produced final result
__device__ float4 g_selbox[BB][MAXDET];
__device__ float  g_selscore[BB][MAXDET];
__device__ int    g_selidx[BB][MAXDET];
__device__ int    g_selcount[BB];

extern __shared__ float4 sm4[];         // dynamic smem (both nms kernels)

// ---------------------------------------------------------------------------
__global__ void reset_kernel()
{
    if (threadIdx.x < BB) {
        g_count[threadIdx.x]    = 0;
        g_hicount[threadIdx.x]  = 0;
        g_selcount[threadIdx.x] = 0;
        g_done[threadIdx.x]     = 0;
    }
}

// ---------------------------------------------------------------------------
// Kernel 1: UNORDERED parallel compaction into (a) full >=0.5 list and
// (b) hi >=T_HI list. Tie-breaks live inside the u64 key.
// ---------------------------------------------------------------------------
__global__ void __launch_bounds__(256)
compact_kernel(const float* __restrict__ boxes, const float* __restrict__ obj)
{
    const int b = blockIdx.y;
    const int n = blockIdx.x * 256 + threadIdx.x;
    const int lane = threadIdx.x & 31;

    bool p = false;
    float sc = 0.0f;
    if (n < NN) {
        sc = obj[(size_t)b * NN + n];
        p = (sc >= 0.5f);
    }

    float4 cor = make_float4(0.f, 0.f, 0.f, 0.f);
    if (p) {
        const float4* bx4 = reinterpret_cast<const float4*>(boxes);
        float4 v = bx4[(size_t)b * NN + n];        // (x, y, w, h)
        float hx = 0.5f * v.z;
        float hy = 0.5f * v.w;
        cor = make_float4(v.x - hx, v.y - hy, v.x + hx, v.y + hy);
    }

    // full list
    unsigned ball = __ballot_sync(0xffffffffu, p);
    int base = 0;
    if (lane == 0 && ball) base = atomicAdd(&g_count[b], __popc(ball));
    base = __shfl_sync(0xffffffffu, base, 0);
    if (p) {
        int pos = base + __popc(ball & ((1u << lane) - 1u));
        g_cor[b][pos]  = cor;
        g_meta[b][pos] = make_float2(sc, __int_as_float(n));
    }

    // hi list
    bool ph = p && (sc >= T_HI);
    unsigned ballh = __ballot_sync(0xffffffffu, ph);
    int baseh = 0;
    if (lane == 0 && ballh) baseh = atomicAdd(&g_hicount[b], __popc(ballh));
    baseh = __shfl_sync(0xffffffffu, baseh, 0);
    if (ph) {
        int pos = baseh + __popc(ballh & ((1u << lane) - 1u));
        if (pos < CAP_HI) {
            g_hicor[b][pos] = cor;
            g_hikey[b][pos] = ((ull)__float_as_uint(sc) << 32)
                            | (ull)(0xFFFFFFFFu - (unsigned)n);
        }
    }
}

// ---------------------------------------------------------------------------
// Kernel 2: greedy NMS over the hi subset. One CTA/batch, 1024 threads,
// 2 syncthreads/round. Suppressed slots zero their key (no mask).
// ---------------------------------------------------------------------------
__global__ void __launch_bounds__(1024, 1)
nms_hi_kernel()
{
    const int b    = blockIdx.x;
    const int tid  = threadIdx.x;
    const int wid  = tid >> 5;
    const int lane = tid & 31;

    __shared__ ull s_wkey[32];
    __shared__ int s_wslot[32];

    const int hcnt = g_hicount[b];
    if (hcnt > CAP_HI) return;           // overflow (statistically never) -> fallback
    const int kmax = (hcnt + 1023) >> 10;

    ull   key[KH];
    float area[KH];
    #pragma unroll
    for (int k = 0; k < KH; k++) {
        int slot = (k << 10) + tid;
        key[k] = 0ull;
        area[k] = 0.0f;
        if (slot < hcnt) {
            float4 c = g_hicor[b][slot];
            sm4[slot] = c;
            key[k] = g_hikey[b][slot];
            area[k] = (c.z - c.x) * (c.w - c.y);
        } else if (slot < (kmax << 10)) {
            sm4[slot] = make_float4(0.f, 0.f, 0.f, 0.f);
        }
    }
    __syncthreads();

    float4 W = make_float4(2.f, 2.f, 2.f, 2.f);   // overlaps nothing
    float Wa = 0.f;
    int ndet = 0;

    for (int it = 0; it < MAXDET; it++) {
        ull bk = 0ull;
        int bslot = 0;

        // fused suppress + local argmax
        for (int k = 0; k < kmax; k++) {
            int slot = (k << 10) + tid;
            float4 c = sm4[slot];
            float ltx = fmaxf(W.x, c.x);
            float lty = fmaxf(W.y, c.y);
            float rbx = fminf(W.z, c.z);
            float rby = fminf(W.w, c.w);
            float w = fmaxf(rbx - ltx, 0.0f);
            float h = fmaxf(rby - lty, 0.0f);
            float inter = w * h;
            float denom = Wa + area[k] - inter + 1e-9f;
            if (inter > 0.5f * denom) key[k] = 0ull;   // suppress
            if (key[k] > bk) { bk = key[k]; bslot = slot; }
        }

        // stage 1: warp reduce -> partials
        #pragma unroll
        for (int off = 16; off; off >>= 1) {
            ull ok = __shfl_down_sync(0xffffffffu, bk, off);
            int os = __shfl_down_sync(0xffffffffu, bslot, off);
            if (ok > bk) { bk = ok; bslot = os; }
        }
        if (lane == 0) { s_wkey[wid] = bk; s_wslot[wid] = bslot; }
        __syncthreads();                               // sync 1

        // stage 2: every warp reduces the 32 partials (butterfly -> all lanes)
        ull wk = s_wkey[lane];
        int ws = s_wslot[lane];
        #pragma unroll
        for (int off = 16; off; off >>= 1) {
            ull ok = __shfl_xor_sync(0xffffffffu, wk, off);
            int os = __shfl_xor_sync(0xffffffffu, ws, off);
            if (ok > wk) { wk = ok; ws = os; }
        }

        if (wk == 0ull) break;                         // hi set exhausted

        float4 Wn = sm4[ws];                           // broadcast LDS
        W = Wn;
        Wa = (W.z - W.x) * (W.w - W.y);
        ndet = it + 1;

        if (tid == 0) {
            g_selbox[b][it]   = W;
            g_selscore[b][it] = __uint_as_float((unsigned)(wk >> 32));
            g_selidx[b][it]   = (int)(0xFFFFFFFFu - (unsigned)wk);
        }
        if ((ws & 1023) == tid) key[ws >> 10] = 0ull;  // winner self-clear
        __syncthreads();                               // sync 2 (protect partials)
    }

    if (tid == 0) {
        g_selcount[b] = ndet;
        g_done[b] = (ndet == MAXDET) ? 1 : 0;          // else fallback recomputes
    }
}

// ---------------------------------------------------------------------------
// Kernel 3: exact full-list fallback (R3 kernel + done-guard). Runs only if
// the hi path could not finalize; recomputes everything from scratch.
// ---------------------------------------------------------------------------
__global__ void __launch_bounds__(1024, 1)
nms_fallback_kernel()
{
    const int b    = blockIdx.x;
    if (g_done[b]) return;

    const int tid  = threadIdx.x;
    const int wid  = tid >> 5;
    const int lane = tid & 31;

    __shared__ ull  s_wkey[32];
    __shared__ int  s_wslot[32];
    __shared__ ull  s_winkey;
    __shared__ int  s_winslot;
    __shared__ float4 s_ovf;

    const int cnt = g_count[b];

    ull key[KS];
    unsigned mask = 0u;
    #pragma unroll
    for (int k = 0; k < KS; k++) {
        int slot = (k << 10) + tid;
        key[k] = 0ull;
        if (slot < cnt) {
            sm4[slot] = g_cor[b][slot];
            float2 m = g_meta[b][slot];
            key[k] = ((ull)__float_as_uint(m.x) << 32)
                   | (ull)(0xFFFFFFFFu - __float_as_uint(m.y));
            mask |= (1u << k);
        } else {
            sm4[slot] = make_float4(0.f, 0.f, 0.f, 0.f);
        }
    }
    unsigned mask2 = 0u;
    const int kg_max = (cnt > CAP_S) ? ((cnt - CAP_S + 1023) >> 10) : 0;
    for (int kg = 0; kg < kg_max; kg++) {
        if (CAP_S + (kg << 10) + tid < cnt) mask2 |= (1u << kg);
    }
    __syncthreads();

    float4 W = make_float4(2.f, 2.f, 2.f, 2.f);
    float Wa = 0.f;

    for (int it = 0; it < MAXDET; it++) {
        ull bk = 0ull;
        int bslot = 0;

        #pragma unroll
        for (int k = 0; k < KS; k++) {
            int slot = (k << 10) + tid;
            float4 c = sm4[slot];
            float ltx = fmaxf(W.x, c.x);
            float lty = fmaxf(W.y, c.y);
            float rbx = fminf(W.z, c.z);
            float rby = fminf(W.w, c.w);
            float w = fmaxf(rbx - ltx, 0.0f);
            float h = fmaxf(rby - lty, 0.0f);
            float inter = w * h;
            float a2 = (c.z - c.x) * (c.w - c.y);
            float denom = Wa + a2 - inter + 1e-9f;
            bool sup = inter > 0.5f * denom;
            if (sup) mask &= ~(1u << k);
            if (((mask >> k) & 1u) && key[k] > bk) { bk = key[k]; bslot = slot; }
        }
        for (int kg = 0; kg < kg_max; kg++) {
            if ((mask2 >> kg) & 1u) {
                int slot = CAP_S + (kg << 10) + tid;
                float4 c = g_cor[b][slot];
                float ltx = fmaxf(W.x, c.x);
                float lty = fmaxf(W.y, c.y);
                float rbx = fminf(W.z, c.z);
                float rby = fminf(W.w, c.w);
                float w = fmaxf(rbx - ltx, 0.0f);
                float h = fmaxf(rby - lty, 0.0f);
                float inter = w * h;
                float a2 = (c.z - c.x) * (c.w - c.y);
                float denom = Wa + a2 - inter + 1e-9f;
                if (inter > 0.5f * denom) {
                    mask2 &= ~(1u << kg);
                } else {
                    float2 m = g_meta[b][slot];
                    ull kk = ((ull)__float_as_uint(m.x) << 32)
                           | (ull)(0xFFFFFFFFu - __float_as_uint(m.y));
                    if (kk > bk) { bk = kk; bslot = slot; }
                }
            }
        }

        #pragma unroll
        for (int off = 16; off; off >>= 1) {
            ull ok = __shfl_down_sync(0xffffffffu, bk, off);
            int os = __shfl_down_sync(0xffffffffu, bslot, off);
            if (ok > bk) { bk = ok; bslot = os; }
        }
        if (lane == 0) { s_wkey[wid] = bk; s_wslot[wid] = bslot; }
        __syncthreads();

        if (wid == 0) {
            ull k2 = s_wkey[lane];
            int sl2 = s_wslot[lane];
            #pragma unroll
            for (int off = 16; off; off >>= 1) {
                ull ok = __shfl_down_sync(0xffffffffu, k2, off);
                int os = __shfl_down_sync(0xffffffffu, sl2, off);
                if (ok > k2) { k2 = ok; sl2 = os; }
            }
            if (lane == 0) { s_winkey = k2; s_winslot = sl2; }
        }
        __syncthreads();

        const ull wk = s_winkey;
        if (wk == 0ull) break;
        const int ws = s_winslot;

        if (ws < CAP_S) {
            W = sm4[ws];
        } else {
            if ((ws & 1023) == tid) s_ovf = g_cor[b][ws];
            __syncthreads();
            W = s_ovf;
        }
        Wa = (W.z - W.x) * (W.w - W.y);

        if (tid == 0) {
            g_selbox[b][it]   = W;
            g_selscore[b][it] = __uint_as_float((unsigned)(wk >> 32));
            g_selidx[b][it]   = (int)(0xFFFFFFFFu - (unsigned)wk);
            g_selcount[b]     = it + 1;
        }
        if ((ws & 1023) == tid) {
            if (ws < CAP_S) mask  &= ~(1u << (ws >> 10));
            else            mask2 &= ~(1u << ((ws - CAP_S) >> 10));
        }
    }
}

// ---------------------------------------------------------------------------
// Kernel 4: write outputs. One warp per (batch, det). Zeros past count.
// ---------------------------------------------------------------------------
__global__ void __launch_bounds__(256)
write_kernel(const float* __restrict__ class_prob, float* __restrict__ out)
{
    int gw   = (blockIdx.x * blockDim.x + threadIdx.x) >> 5;
    int lane = threadIdx.x & 31;

    if (gw < BB * MAXDET) {
        int b = gw / MAXDET;
        int i = gw - b * MAXDET;
        bool valid = (i < g_selcount[b]);

        float4 box = make_float4(0.f, 0.f, 0.f, 0.f);
        float scv = 0.0f;
        int orig = 0;
        if (valid) {
            box  = g_selbox[b][i];
            scv  = g_selscore[b][i];
            orig = g_selidx[b][i];
        }

        if (lane == 0) {
            float* p = out + OFF_BOX + (size_t)(b * MAXDET + i) * 4;
            p[0] = box.x; p[1] = box.y; p[2] = box.z; p[3] = box.w;
            out[OFF_SCORE + b * MAXDET + i] = scv;
        }
        const float* cp = class_prob + ((size_t)b * NN + orig) * CC;
        float* co = out + OFF_CLS + (size_t)(b * MAXDET + i) * CC;
        #pragma unroll
        for (int c = lane; c < CC; c += 32) {
            co[c] = valid ? cp[c] : 0.0f;
        }
    }

    if (blockIdx.x == 0 && threadIdx.x < BB) {
        out[OFF_CNT + threadIdx.x] = (float)g_selcount[threadIdx.x];
    }
}

// ---------------------------------------------------------------------------
extern "C" void kernel_launch(void* const* d_in, const int* in_sizes, int n_in,
                              void* d_out, int out_size)
{
    const float* boxes = (const float*)d_in[0];   // (16, 25200, 4)
    const float* obj   = (const float*)d_in[1];   // (16, 25200, 1)
    const float* cls   = (const float*)d_in[2];   // (16, 25200, 80)
    float* out = (float*)d_out;

    static bool attr_done = false;
    if (!attr_done) {
        cudaFuncSetAttribute(nms_hi_kernel,
                             cudaFuncAttributeMaxDynamicSharedMemorySize,
                             CAP_HI * (int)sizeof(float4));
        cudaFuncSetAttribute(nms_fallback_kernel,
                             cudaFuncAttributeMaxDynamicSharedMemorySize,
                             CAP_S * (int)sizeof(float4));
        attr_done = true;
    }

    reset_kernel<<<1, 32>>>();
    compact_kernel<<<dim3((NN + 255) / 256, BB), 256>>>(boxes, obj);
    nms_hi_kernel<<<BB, 1024, CAP_HI * sizeof(float4)>>>();
    nms_fallback_kernel<<<BB, 1024, CAP_S * sizeof(float4)>>>();
    write_kernel<<<(BB * MAXDET * 32 + 255) / 256, 256>>>(cls, out);
}

// round 5
// speedup vs baseline: 35.7280x; 3.9699x over previous
#include <cuda_runtime.h>
#include <stdint.h>

// Problem constants
#define BB 16
#define NN 25200
#define CC 80
#define MAXDET 100

// Bucketed hi-subset (exact prefix of greedy; fallback guards all tails)
#define T_BKT 0.95f
#define NB 128               // buckets over [0.95, 1.0)
#define BSCALE 2560.0f       // NB / 0.05
#define BCAP 32              // per-bucket capacity (lambda ~9.8)
#define SCAP 2048            // sorted stream capacity (expected ~1260)

// Fallback full list
#define CAP_S 13312
#define KS 13

// Output layout (flattened concat, float32):
#define OFF_BOX   0
#define OFF_SCORE 6400
#define OFF_CLS   8000
#define OFF_CNT   136000

typedef unsigned long long ull;

// ---------------- scratch (__device__ globals: no allocs) -------------------
__device__ float4 g_cor[BB][NN];          // full compacted corners (fallback)
__device__ float2 g_meta[BB][NN];         // full (score, idx bits)
__device__ int    g_count[BB];
__device__ ull    g_bkey[BB][NB][BCAP];   // bucket keys
__device__ float4 g_bcor[BB][NB][BCAP];   // bucket corners
__device__ int    g_bcnt[BB][NB];
__device__ int    g_bovf[BB];
__device__ int    g_done[BB];
__device__ float4 g_selbox[BB][MAXDET];
__device__ float  g_selscore[BB][MAXDET];
__device__ int    g_selidx[BB][MAXDET];
__device__ int    g_selcount[BB];

// ---------------------------------------------------------------------------
__global__ void __launch_bounds__(NB)
reset_kernel()
{
    int b = blockIdx.x;
    g_bcnt[b][threadIdx.x] = 0;
    if (threadIdx.x == 0) {
        g_count[b] = 0;
        g_bovf[b] = 0;
        g_done[b] = 0;
        g_selcount[b] = 0;
    }
}

// ---------------------------------------------------------------------------
// Kernel 1: compaction into (a) full >=0.5 list (fallback) and (b) score
// buckets for >= T_BKT. Bucket map is monotone in score; u64 key carries the
// exact (score desc, idx asc) tie-break.
// ---------------------------------------------------------------------------
__global__ void __launch_bounds__(256)
compact_kernel(const float* __restrict__ boxes, const float* __restrict__ obj)
{
    const int b = blockIdx.y;
    const int n = blockIdx.x * 256 + threadIdx.x;
    const int lane = threadIdx.x & 31;

    bool p = false;
    float sc = 0.0f;
    if (n < NN) {
        sc = obj[(size_t)b * NN + n];
        p = (sc >= 0.5f);
    }

    float4 cor = make_float4(0.f, 0.f, 0.f, 0.f);
    if (p) {
        const float4* bx4 = reinterpret_cast<const float4*>(boxes);
        float4 v = bx4[(size_t)b * NN + n];        // (x, y, w, h)
        float hx = 0.5f * v.z;
        float hy = 0.5f * v.w;
        cor = make_float4(v.x - hx, v.y - hy, v.x + hx, v.y + hy);
    }

    // full list (warp-aggregated)
    unsigned ball = __ballot_sync(0xffffffffu, p);
    int base = 0;
    if (lane == 0 && ball) base = atomicAdd(&g_count[b], __popc(ball));
    base = __shfl_sync(0xffffffffu, base, 0);
    if (p) {
        int pos = base + __popc(ball & ((1u << lane) - 1u));
        g_cor[b][pos]  = cor;
        g_meta[b][pos] = make_float2(sc, __int_as_float(n));
    }

    // bucket scatter
    if (p && sc >= T_BKT) {
        int bk = (int)((sc - T_BKT) * BSCALE);
        bk = bk > (NB - 1) ? (NB - 1) : (bk < 0 ? 0 : bk);
        int pos = atomicAdd(&g_bcnt[b][bk], 1);
        if (pos < BCAP) {
            g_bkey[b][bk][pos] = ((ull)__float_as_uint(sc) << 32)
                               | (ull)(0xFFFFFFFFu - (unsigned)n);
            g_bcor[b][bk][pos] = cor;
        } else {
            g_bovf[b] = 1;
        }
    }
}

// ---------------------------------------------------------------------------
// Kernel 2: sorted lazy greedy NMS.
//  Phase 1 (32 warps): per-bucket in-warp bitonic sort32 -> smem stream in
//                      exact descending key order.
//  Phase 2 (warp 0):   batched serial greedy walk over the stream.
// Dynamic smem: skey ull[SCAP] (16KB) + scor float4[SCAP] (32KB) = 48KB.
// ---------------------------------------------------------------------------
extern __shared__ ull dyn_smem[];

__global__ void __launch_bounds__(1024, 1)
nms_sorted_kernel()
{
    const int b    = blockIdx.x;
    const int tid  = threadIdx.x;
    const int wid  = tid >> 5;
    const int lane = tid & 31;

    if (g_bovf[b]) return;                      // fallback handles (done=0)

    ull*    skey = dyn_smem;                    // [SCAP]
    float4* scor = (float4*)(dyn_smem + SCAP);  // [SCAP]

    __shared__ int s_cnt[NB];
    __shared__ int s_off[NB];
    __shared__ int s_ws[4];
    __shared__ int s_len;
    __shared__ int s_bad;
    __shared__ float4 acor[MAXDET];
    __shared__ float  aarea[MAXDET];

    if (tid == 0) s_bad = 0;
    if (tid < NB) s_cnt[tid] = g_bcnt[b][tid];
    __syncthreads();

    // offsets (descending-bucket exclusive scan): off[bk] = sum_{j>bk} cnt[j]
    if (tid < NB) {
        int r = tid;                            // descending rank
        int v = s_cnt[NB - 1 - r];
        if (v > BCAP) s_bad = 1;
        int x = v;
        #pragma unroll
        for (int o = 1; o < 32; o <<= 1) {
            int y = __shfl_up_sync(0xffffffffu, x, o);
            if (lane >= o) x += y;
        }
        if (lane == 31) s_ws[wid] = x;
    }
    __syncthreads();
    if (tid < NB) {
        int r = tid;
        int v = s_cnt[NB - 1 - r];
        int add = 0;
        #pragma unroll
        for (int w = 0; w < 4; w++) if (w < wid) add += s_ws[w];
        int incl = (({ int x = v;
            #pragma unroll
            for (int o = 1; o < 32; o <<= 1) {
                int y = __shfl_up_sync(0xffffffffu, x, o);
                if (lane >= o) x += y;
            } x; })) + add;
        s_off[NB - 1 - r] = incl - v;
        if (r == NB - 1) s_len = incl;
    }
    __syncthreads();

    const int streamLen = s_len;
    if (s_bad || streamLen > SCAP) return;      // fallback handles

    // Phase 1: per-bucket sort (warp w handles buckets w, w+32, ...)
    for (int bk = wid; bk < NB; bk += 32) {
        int n = s_cnt[bk];
        if (n == 0) continue;
        ull k = (lane < n) ? ~g_bkey[b][bk][lane] : ~0ull;  // ~key: asc == key desc
        int v = lane;
        #pragma unroll
        for (int sz = 2; sz <= 32; sz <<= 1) {
            #pragma unroll
            for (int j = sz >> 1; j > 0; j >>= 1) {
                ull pk = __shfl_xor_sync(0xffffffffu, k, j);
                int pv = __shfl_xor_sync(0xffffffffu, v, j);
                bool up = ((lane & sz) == 0);
                bool takeMax = (((lane & j) != 0) == up);
                bool take = takeMax ? (pk > k) : (pk < k);
                if (take) { k = pk; v = pv; }
            }
        }
        if (lane < n) {
            int o = s_off[bk] + lane;
            skey[o] = ~k;
            scor[o] = g_bcor[b][bk][v];
        }
    }
    __syncthreads();

    // Phase 2: batched serial greedy walk (warp 0 only)
    if (wid == 0) {
        int accN = 0;
        int pos = 0;
        while (accN < MAXDET && pos < streamLen) {
            int myPos = pos + lane;
            bool valid = myPos < streamLen;
            float4 c = valid ? scor[myPos] : make_float4(3.f, 3.f, 3.f, 3.f);
            ull    k = valid ? skey[myPos] : 0ull;
            float a2 = (c.z - c.x) * (c.w - c.y);

            // conflict vs accepted list
            bool confA = !valid;
            for (int a = 0; a < accN; a++) {
                float4 W = acor[a];
                float Wa = aarea[a];
                float ltx = fmaxf(W.x, c.x);
                float lty = fmaxf(W.y, c.y);
                float rbx = fminf(W.z, c.z);
                float rby = fminf(W.w, c.w);
                float w = fmaxf(rbx - ltx, 0.0f);
                float h = fmaxf(rby - lty, 0.0f);
                float inter = w * h;
                float denom = Wa + a2 - inter + 1e-9f;
                if (inter > 0.5f * denom) confA = true;
            }

            // pairwise intra-batch conflicts (symmetric; self masked in walk)
            unsigned pc = 0u;
            #pragma unroll
            for (int j = 0; j < 32; j++) {
                float jx = __shfl_sync(0xffffffffu, c.x, j);
                float jy = __shfl_sync(0xffffffffu, c.y, j);
                float jz = __shfl_sync(0xffffffffu, c.z, j);
                float jw = __shfl_sync(0xffffffffu, c.w, j);
                float ja = __shfl_sync(0xffffffffu, a2, j);
                float ltx = fmaxf(jx, c.x);
                float lty = fmaxf(jy, c.y);
                float rbx = fminf(jz, c.z);
                float rby = fminf(jw, c.w);
                float w = fmaxf(rbx - ltx, 0.0f);
                float h = fmaxf(rby - lty, 0.0f);
                float inter = w * h;
                float denom = ja + a2 - inter + 1e-9f;
                if (inter > 0.5f * denom) pc |= (1u << j);
            }

            // gather all lanes' (confA, pc), then redundant register walk
            ull mine = ((ull)(confA ? 1u : 0u) << 32) | (ull)pc;
            unsigned batchAcc = 0u;
            int cap = MAXDET - accN;
            #pragma unroll
            for (int j = 0; j < 32; j++) {
                ull mj = __shfl_sync(0xffffffffu, mine, j);
                bool okA = ((mj >> 32) & 1ull) == 0ull;
                unsigned pcj = (unsigned)mj;
                bool ok = okA
                       && ((pcj & batchAcc & ~(1u << j)) == 0u)
                       && (__popc(batchAcc) < cap);
                if (ok) batchAcc |= (1u << j);
            }

            // append accepted (order-preserving)
            if ((batchAcc >> lane) & 1u) {
                int rank = __popc(batchAcc & ((1u << lane) - 1u));
                int o = accN + rank;
                acor[o] = c;
                aarea[o] = a2;
                g_selbox[b][o]   = c;
                g_selscore[b][o] = __uint_as_float((unsigned)(k >> 32));
                g_selidx[b][o]   = (int)(0xFFFFFFFFu - (unsigned)k);
            }
            __syncwarp();
            accN += __popc(batchAcc);
            pos += 32;
        }
        if (lane == 0) {
            g_selcount[b] = accN;
            g_done[b] = (accN == MAXDET) ? 1 : 0;
        }
    }
}

// ---------------------------------------------------------------------------
// Kernel 3: exact full-list fallback (proven R3/R4 kernel + done-guard).
// ---------------------------------------------------------------------------
extern __shared__ float4 sm4[];

__global__ void __launch_bounds__(1024, 1)
nms_fallback_kernel()
{
    const int b = blockIdx.x;
    if (g_done[b]) return;

    const int tid  = threadIdx.x;
    const int wid  = tid >> 5;
    const int lane = tid & 31;

    __shared__ ull  s_wkey[32];
    __shared__ int  s_wslot[32];
    __shared__ ull  s_winkey;
    __shared__ int  s_winslot;
    __shared__ float4 s_ovf;

    const int cnt = g_count[b];

    ull key[KS];
    unsigned mask = 0u;
    #pragma unroll
    for (int k = 0; k < KS; k++) {
        int slot = (k << 10) + tid;
        key[k] = 0ull;
        if (slot < cnt) {
            sm4[slot] = g_cor[b][slot];
            float2 m = g_meta[b][slot];
            key[k] = ((ull)__float_as_uint(m.x) << 32)
                   | (ull)(0xFFFFFFFFu - __float_as_uint(m.y));
            mask |= (1u << k);
        } else {
            sm4[slot] = make_float4(0.f, 0.f, 0.f, 0.f);
        }
    }
    unsigned mask2 = 0u;
    const int kg_max = (cnt > CAP_S) ? ((cnt - CAP_S + 1023) >> 10) : 0;
    for (int kg = 0; kg < kg_max; kg++) {
        if (CAP_S + (kg << 10) + tid < cnt) mask2 |= (1u << kg);
    }
    __syncthreads();

    float4 W = make_float4(2.f, 2.f, 2.f, 2.f);
    float Wa = 0.f;

    for (int it = 0; it < MAXDET; it++) {
        ull bk = 0ull;
        int bslot = 0;

        #pragma unroll
        for (int k = 0; k < KS; k++) {
            int slot = (k << 10) + tid;
            float4 c = sm4[slot];
            float ltx = fmaxf(W.x, c.x);
            float lty = fmaxf(W.y, c.y);
            float rbx = fminf(W.z, c.z);
            float rby = fminf(W.w, c.w);
            float w = fmaxf(rbx - ltx, 0.0f);
            float h = fmaxf(rby - lty, 0.0f);
            float inter = w * h;
            float a2 = (c.z - c.x) * (c.w - c.y);
            float denom = Wa + a2 - inter + 1e-9f;
            bool sup = inter > 0.5f * denom;
            if (sup) mask &= ~(1u << k);
            if (((mask >> k) & 1u) && key[k] > bk) { bk = key[k]; bslot = slot; }
        }
        for (int kg = 0; kg < kg_max; kg++) {
            if ((mask2 >> kg) & 1u) {
                int slot = CAP_S + (kg << 10) + tid;
                float4 c = g_cor[b][slot];
                float ltx = fmaxf(W.x, c.x);
                float lty = fmaxf(W.y, c.y);
                float rbx = fminf(W.z, c.z);
                float rby = fminf(W.w, c.w);
                float w = fmaxf(rbx - ltx, 0.0f);
                float h = fmaxf(rby - lty, 0.0f);
                float inter = w * h;
                float a2 = (c.z - c.x) * (c.w - c.y);
                float denom = Wa + a2 - inter + 1e-9f;
                if (inter > 0.5f * denom) {
                    mask2 &= ~(1u << kg);
                } else {
                    float2 m = g_meta[b][slot];
                    ull kk = ((ull)__float_as_uint(m.x) << 32)
                           | (ull)(0xFFFFFFFFu - __float_as_uint(m.y));
                    if (kk > bk) { bk = kk; bslot = slot; }
                }
            }
        }

        #pragma unroll
        for (int off = 16; off; off >>= 1) {
            ull ok = __shfl_down_sync(0xffffffffu, bk, off);
            int os = __shfl_down_sync(0xffffffffu, bslot, off);
            if (ok > bk) { bk = ok; bslot = os; }
        }
        if (lane == 0) { s_wkey[wid] = bk; s_wslot[wid] = bslot; }
        __syncthreads();

        if (wid == 0) {
            ull k2 = s_wkey[lane];
            int sl2 = s_wslot[lane];
            #pragma unroll
            for (int off = 16; off; off >>= 1) {
                ull ok = __shfl_down_sync(0xffffffffu, k2, off);
                int os = __shfl_down_sync(0xffffffffu, sl2, off);
                if (ok > k2) { k2 = ok; sl2 = os; }
            }
            if (lane == 0) { s_winkey = k2; s_winslot = sl2; }
        }
        __syncthreads();

        const ull wk = s_winkey;
        if (wk == 0ull) break;
        const int ws = s_winslot;

        if (ws < CAP_S) {
            W = sm4[ws];
        } else {
            if ((ws & 1023) == tid) s_ovf = g_cor[b][ws];
            __syncthreads();
            W = s_ovf;
        }
        Wa = (W.z - W.x) * (W.w - W.y);

        if (tid == 0) {
            g_selbox[b][it]   = W;
            g_selscore[b][it] = __uint_as_float((unsigned)(wk >> 32));
            g_selidx[b][it]   = (int)(0xFFFFFFFFu - (unsigned)wk);
            g_selcount[b]     = it + 1;
        }
        if ((ws & 1023) == tid) {
            if (ws < CAP_S) mask  &= ~(1u << (ws >> 10));
            else            mask2 &= ~(1u << ((ws - CAP_S) >> 10));
        }
    }
}

// ---------------------------------------------------------------------------
// Kernel 4: write outputs. One warp per (batch, det). Zeros past count.
// ---------------------------------------------------------------------------
__global__ void __launch_bounds__(256)
write_kernel(const float* __restrict__ class_prob, float* __restrict__ out)
{
    int gw   = (blockIdx.x * blockDim.x + threadIdx.x) >> 5;
    int lane = threadIdx.x & 31;

    if (gw < BB * MAXDET) {
        int b = gw / MAXDET;
        int i = gw - b * MAXDET;
        bool valid = (i < g_selcount[b]);

        float4 box = make_float4(0.f, 0.f, 0.f, 0.f);
        float scv = 0.0f;
        int orig = 0;
        if (valid) {
            box  = g_selbox[b][i];
            scv  = g_selscore[b][i];
            orig = g_selidx[b][i];
        }

        if (lane == 0) {
            float* p = out + OFF_BOX + (size_t)(b * MAXDET + i) * 4;
            p[0] = box.x; p[1] = box.y; p[2] = box.z; p[3] = box.w;
            out[OFF_SCORE + b * MAXDET + i] = scv;
        }
        const float* cp = class_prob + ((size_t)b * NN + orig) * CC;
        float* co = out + OFF_CLS + (size_t)(b * MAXDET + i) * CC;
        #pragma unroll
        for (int c = lane; c < CC; c += 32) {
            co[c] = valid ? cp[c] : 0.0f;
        }
    }

    if (blockIdx.x == 0 && threadIdx.x < BB) {
        out[OFF_CNT + threadIdx.x] = (float)g_selcount[threadIdx.x];
    }
}

// ---------------------------------------------------------------------------
extern "C" void kernel_launch(void* const* d_in, const int* in_sizes, int n_in,
                              void* d_out, int out_size)
{
    const float* boxes = (const float*)d_in[0];   // (16, 25200, 4)
    const float* obj   = (const float*)d_in[1];   // (16, 25200, 1)
    const float* cls   = (const float*)d_in[2];   // (16, 25200, 80)
    float* out = (float*)d_out;

    const int sortedSmem = SCAP * (int)(sizeof(ull) + sizeof(float4));  // 48KB
    const int fbSmem     = CAP_S * (int)sizeof(float4);                 // 208KB

    static bool attr_done = false;
    if (!attr_done) {
        cudaFuncSetAttribute(nms_sorted_kernel,
                             cudaFuncAttributeMaxDynamicSharedMemorySize,
                             sortedSmem);
        cudaFuncSetAttribute(nms_fallback_kernel,
                             cudaFuncAttributeMaxDynamicSharedMemorySize,
                             fbSmem);
        attr_done = true;
    }

    reset_kernel<<<BB, NB>>>();
    compact_kernel<<<dim3((NN + 255) / 256, BB), 256>>>(boxes, obj);
    nms_sorted_kernel<<<BB, 1024, sortedSmem>>>();
    nms_fallback_kernel<<<BB, 1024, fbSmem>>>();
    write_kernel<<<(BB * MAXDET * 32 + 255) / 256, 256>>>(cls, out);
}